// round 6
// baseline (speedup 1.0000x reference)
#include <cuda_runtime.h>
#include <cuda_bf16.h>

// DecayModel: out[b,s,h] = (fwd[s] + bwd[s]) / norm[s] per (b,h) column.
// fwd[s] = sum_{k<=s} 0.5^{s-k} x[k];  bwd[s] = sum_{k>=s} 0.5^{k-s} x[k];
// norm[s] = 4 - 2^-s - 2^-(S-1-s)  (== 4.0f exactly in fp32 away from ends).
//
// Forward-state-carry variant: each thread owns one h column and a SPAN=256
// range of S, processed as 8 chunks of 32 with ping-pong register buffers.
// The fwd recurrence carries across chunks (no left-halo re-read per chunk);
// the next chunk's buffer doubles as the right halo for the current chunk's
// backward warmup (HALO=20, truncation < 2^-20). Read amplification through
// L1/L2 is (256+40)/256 = 1.16x; DRAM traffic is exactly 1 read + 1 write
// per element. x reconstructed in the bwd pass via x[t] = fwd[t]-0.5*fwd[t-1].

#define S_DIM 2048
#define H_DIM 1024
#define CHUNK 32
#define SPANC 8
#define SPAN  (CHUNK * SPANC)   // 256
#define HALO  20
#define TPB   256

__device__ __forceinline__ void proc_chunk(
    float* __restrict__ oc, int cs, float& y,
    float (&cur)[CHUNK], const float (&nxt)[CHUNK], bool has_right)
{
    // ---- forward scan, in place (cur becomes fwd) ----
    const float y_in = y;
    float yy = y;
    #pragma unroll
    for (int t = 0; t < CHUNK; ++t) {
        yy = fmaf(yy, 0.5f, cur[t]);
        cur[t] = yy;
    }
    y = yy;

    // ---- backward warmup from the next chunk's raw x (right halo) ----
    float z = 0.0f;
    if (has_right) {
        #pragma unroll
        for (int t = HALO - 1; t >= 0; --t)
            z = fmaf(z, 0.5f, nxt[t]);
    }

    // ---- backward scan + combine + normalize + streaming store ----
    const bool boundary = (cs == 0) || (cs + CHUNK == S_DIM);
    if (boundary) {
        // exact norm via exp2f (only the first and last chunk of S)
        #pragma unroll
        for (int t = CHUNK - 1; t >= 0; --t) {
            float prev = (t > 0) ? cur[t - 1] : y_in;
            float xv = fmaf(-0.5f, prev, cur[t]);
            z = fmaf(z, 0.5f, xv);
            int s = cs + t;
            float rn = 1.0f / (4.0f - exp2f(-(float)s)
                                    - exp2f(-(float)(S_DIM - 1 - s)));
            __stcs(&oc[(size_t)s * H_DIM], (cur[t] + z) * rn);
        }
    } else {
        // interior: norm == 4.0f exactly in fp32
        #pragma unroll
        for (int t = CHUNK - 1; t >= 0; --t) {
            float prev = (t > 0) ? cur[t - 1] : y_in;
            float xv = fmaf(-0.5f, prev, cur[t]);
            z = fmaf(z, 0.5f, xv);
            __stcs(&oc[(size_t)(cs + t) * H_DIM], (cur[t] + z) * 0.25f);
        }
    }
}

__global__ __launch_bounds__(TPB, 2)
void decay_model_kernel(const float* __restrict__ x, float* __restrict__ out) {
    const int h  = blockIdx.x * TPB + threadIdx.x;   // h column (coalesced)
    const int s0 = blockIdx.y * SPAN;                // span start along S
    const size_t base = (size_t)blockIdx.z * S_DIM * H_DIM + h;
    const float* __restrict__ xc = x + base;
    float* __restrict__ oc = out + base;

    // ---- left-halo warmup, once per span ----
    float y = 0.0f;
    if (s0 != 0) {
        #pragma unroll
        for (int t = 0; t < HALO; ++t)
            y = fmaf(y, 0.5f, xc[(size_t)(s0 - HALO + t) * H_DIM]);
    }

    float buf[2][CHUNK];
    const bool last_span = (s0 + SPAN == S_DIM);

    // load chunk 0 into buf[0]
    #pragma unroll
    for (int t = 0; t < CHUNK; ++t)
        buf[0][t] = xc[(size_t)(s0 + t) * H_DIM];

    // chunks 0 .. SPANC-2: prefetch next chunk, then process current
    #pragma unroll
    for (int j = 0; j < SPANC - 1; ++j) {
        float (&cur)[CHUNK] = buf[j & 1];
        float (&nxt)[CHUNK] = buf[(j + 1) & 1];
        #pragma unroll
        for (int t = 0; t < CHUNK; ++t)
            nxt[t] = xc[(size_t)(s0 + (j + 1) * CHUNK + t) * H_DIM];
        proc_chunk(oc, s0 + j * CHUNK, y, cur, nxt, true);
    }

    // last chunk of span: right halo comes from the next span (if any)
    {
        float (&cur)[CHUNK] = buf[(SPANC - 1) & 1];
        float (&nxt)[CHUNK] = buf[SPANC & 1];
        if (!last_span) {
            #pragma unroll
            for (int t = 0; t < HALO; ++t)
                nxt[t] = xc[(size_t)(s0 + SPAN + t) * H_DIM];
        }
        proc_chunk(oc, s0 + (SPANC - 1) * CHUNK, y, cur, nxt, !last_span);
    }
}

extern "C" void kernel_launch(void* const* d_in, const int* in_sizes, int n_in,
                              void* d_out, int out_size) {
    const float* x = (const float*)d_in[0];
    float* out = (float*)d_out;
    const int B = in_sizes[0] / (S_DIM * H_DIM);

    dim3 grid(H_DIM / TPB, S_DIM / SPAN, B);   // (4, 8, B) = 512 blocks
    decay_model_kernel<<<grid, TPB>>>(x, out);
}

// round 7
// speedup vs baseline: 1.0437x; 1.0437x over previous
#include <cuda_runtime.h>
#include <cuda_bf16.h>

// DecayModel: out[b,s,h] = (fwd[s] + bwd[s]) / norm[s] per (b,h) column.
// fwd[s] = sum_{k<=s} 0.5^{s-k} x[k];  bwd[s] = sum_{k>=s} 0.5^{k-s} x[k];
// norm[s] = 4 - 2^-s - 2^-(S-1-s)  (== 4.0f exactly in fp32 away from ends).
//
// Forward-state-carry, single-wave variant: each thread owns one h column and
// a SPAN=256 range of S, processed as 16 chunks of 16 with ping-pong register
// buffers. The fwd recurrence carries across chunks; the next chunk's buffer
// IS the right halo (HALO == CHUNK == 16, truncation < 2^-16 << 1e-3 gate).
// Read amplification (256+32)/256 = 1.125x; DRAM traffic 1R+1W per element.
// Low register count (<=62) -> 4 blocks/SM -> the whole 512-block grid is
// resident in a single wave (no wave transitions, no tail ramp).
// Interior loads use __ldcs (read-once chip-wide, evict-first); span-boundary
// chunks keep default caching because the neighbor span re-reads them as halo.

#define S_DIM 2048
#define H_DIM 1024
#define CHUNK 16
#define SPANC 16
#define SPAN  (CHUNK * SPANC)   // 256
#define TPB   256

__device__ __forceinline__ void proc_chunk(
    float* __restrict__ oc, int cs, float& y,
    float (&cur)[CHUNK], const float (&nxt)[CHUNK], bool has_right)
{
    // ---- forward scan, in place (cur becomes fwd) ----
    const float y_in = y;
    float yy = y;
    #pragma unroll
    for (int t = 0; t < CHUNK; ++t) {
        yy = fmaf(yy, 0.5f, cur[t]);
        cur[t] = yy;
    }
    y = yy;

    // ---- backward warmup: the entire next chunk is the right halo ----
    float z = 0.0f;
    if (has_right) {
        #pragma unroll
        for (int t = CHUNK - 1; t >= 0; --t)
            z = fmaf(z, 0.5f, nxt[t]);
    }

    // ---- backward scan + combine + normalize + streaming store ----
    const bool boundary = (cs == 0) || (cs + CHUNK == S_DIM);
    if (boundary) {
        // exact norm via exp2f (only the first and last chunk of S)
        #pragma unroll
        for (int t = CHUNK - 1; t >= 0; --t) {
            float prev = (t > 0) ? cur[t - 1] : y_in;
            float xv = fmaf(-0.5f, prev, cur[t]);
            z = fmaf(z, 0.5f, xv);
            int s = cs + t;
            float rn = 1.0f / (4.0f - exp2f(-(float)s)
                                    - exp2f(-(float)(S_DIM - 1 - s)));
            __stcs(&oc[(size_t)s * H_DIM], (cur[t] + z) * rn);
        }
    } else {
        // interior: norm == 4.0f exactly in fp32
        #pragma unroll
        for (int t = CHUNK - 1; t >= 0; --t) {
            float prev = (t > 0) ? cur[t - 1] : y_in;
            float xv = fmaf(-0.5f, prev, cur[t]);
            z = fmaf(z, 0.5f, xv);
            __stcs(&oc[(size_t)(cs + t) * H_DIM], (cur[t] + z) * 0.25f);
        }
    }
}

__global__ __launch_bounds__(TPB, 4)
void decay_model_kernel(const float* __restrict__ x, float* __restrict__ out) {
    const int h  = blockIdx.x * TPB + threadIdx.x;   // h column (coalesced)
    const int s0 = blockIdx.y * SPAN;                // span start along S
    const size_t base = (size_t)blockIdx.z * S_DIM * H_DIM + h;
    const float* __restrict__ xc = x + base;
    float* __restrict__ oc = out + base;

    // ---- left-halo warmup, once per span (reads neighbor span's tail:
    //      doubly-read chip-wide -> default caching) ----
    float y = 0.0f;
    if (s0 != 0) {
        #pragma unroll
        for (int t = 0; t < CHUNK; ++t)
            y = fmaf(y, 0.5f, xc[(size_t)(s0 - CHUNK + t) * H_DIM]);
    }

    float buf[2][CHUNK];
    const bool last_span = (s0 + SPAN == S_DIM);

    // chunk 0: first CHUNK elements of the span are the left neighbor's halo
    // (doubly read) -> default caching
    #pragma unroll
    for (int t = 0; t < CHUNK; ++t)
        buf[0][t] = xc[(size_t)(s0 + t) * H_DIM];

    // chunks 0 .. SPANC-2: prefetch next chunk, then process current
    #pragma unroll
    for (int j = 0; j < SPANC - 1; ++j) {
        float (&cur)[CHUNK] = buf[j & 1];
        float (&nxt)[CHUNK] = buf[(j + 1) & 1];
        const bool nxt_shared = (j + 1 == SPANC - 1);   // span tail: halo of right neighbor
        if (nxt_shared) {
            #pragma unroll
            for (int t = 0; t < CHUNK; ++t)
                nxt[t] = xc[(size_t)(s0 + (j + 1) * CHUNK + t) * H_DIM];
        } else {
            #pragma unroll
            for (int t = 0; t < CHUNK; ++t)
                nxt[t] = __ldcs(&xc[(size_t)(s0 + (j + 1) * CHUNK + t) * H_DIM]);
        }
        proc_chunk(oc, s0 + j * CHUNK, y, cur, nxt, true);
    }

    // last chunk of span: right halo comes from the next span (if any)
    {
        float (&cur)[CHUNK] = buf[(SPANC - 1) & 1];
        float (&nxt)[CHUNK] = buf[SPANC & 1];
        if (!last_span) {
            #pragma unroll
            for (int t = 0; t < CHUNK; ++t)
                nxt[t] = xc[(size_t)(s0 + SPAN + t) * H_DIM];
        }
        proc_chunk(oc, s0 + (SPANC - 1) * CHUNK, y, cur, nxt, !last_span);
    }
}

extern "C" void kernel_launch(void* const* d_in, const int* in_sizes, int n_in,
                              void* d_out, int out_size) {
    const float* x = (const float*)d_in[0];
    float* out = (float*)d_out;
    const int B = in_sizes[0] / (S_DIM * H_DIM);

    dim3 grid(H_DIM / TPB, S_DIM / SPAN, B);   // (4, 8, B) = 512 blocks
    decay_model_kernel<<<grid, TPB>>>(x, out);
}